// round 3
// baseline (speedup 1.0000x reference)
#include <cuda_runtime.h>

#define N_NODES 25000
#define N_EDGES 400000
#define NGRAPH  128
#define F       64
#define KCAT    192
#define NODE_F  92
#define EDGE_F  41
#define FCDIM   10
#define BN_EPS  1e-5f
#define NTILES  (N_EDGES/64)   /* 6250 */

// ---------------- scratch (device globals; no allocation allowed) ----------
__device__ __align__(128) float g_hn[N_NODES*F];               // 6.4 MB
__device__ __align__(128) float g_he[(size_t)N_EDGES*F];       // 102.4 MB
__device__ __align__(128) float g_z[(size_t)N_EDGES*128];      // 204.8 MB
__device__ __align__(128) float g_agg[N_NODES*F];              // 6.4 MB
__device__ __align__(128) float g_stats[256];                  // sum[128], sumsq[128]
__device__ __align__(128) float g_scale[128];
__device__ __align__(128) float g_shift[128];
__device__ __align__(128) float g_pooled[NGRAPH*F];
__device__ __align__(128) float g_cnt[NGRAPH];

// ---------------- helpers ----------------
__device__ __forceinline__ float sigmoidf_(float x){ return 1.f/(1.f+expf(-x)); }
__device__ __forceinline__ float siluf_(float x){ return x/(1.f+expf(-x)); }
__device__ __forceinline__ float softplusf_(float x){
    return fmaxf(x,0.f) + log1pf(expf(-fabsf(x)));
}

// packed fp32x2 ops (FFMA2 path — PTX-only, ptxas never auto-fuses)
typedef unsigned long long u64;
struct u64x2 { u64 x, y; };

__device__ __forceinline__ u64 dup_f32x2(float a){
    u64 r; asm("mov.b64 %0, {%1, %2};" : "=l"(r) : "f"(a), "f"(a)); return r;
}
__device__ __forceinline__ u64 fma_f32x2(u64 a, u64 b, u64 c){
    u64 d; asm("fma.rn.f32x2 %0, %1, %2, %3;" : "=l"(d) : "l"(a), "l"(b), "l"(c)); return d;
}
__device__ __forceinline__ void unpack_f32x2(u64 v, float& lo, float& hi){
    asm("mov.b64 {%0, %1}, %2;" : "=f"(lo), "=f"(hi) : "l"(v));
}

// ---------------- zero kernels ----------------
__global__ void k_zero_stats(){ int i=threadIdx.x; if(i<256) g_stats[i]=0.f; }
__global__ void k_zero_agg(){ int i=blockIdx.x*256+threadIdx.x; if(i<N_NODES*F) g_agg[i]=0.f; }
__global__ void k_zero_pool(){ int i=blockIdx.x*256+threadIdx.x;
    if(i<NGRAPH*F) g_pooled[i]=0.f; if(i<NGRAPH) g_cnt[i]=0.f; }

// ---------------- embedding GEMM: Z = X @ W + b, plus column stats -------
// tile: 64 rows x 64 cols, K up to 92. target: 0 -> g_hn, 1 -> g_he
__global__ __launch_bounds__(256) void k_embed_gemm(
    const float* __restrict__ X, int rows, int K,
    const float* __restrict__ W, const float* __restrict__ bias, int target)
{
    __shared__ float Ws[NODE_F*64];     // [K][64]
    __shared__ float Xs[NODE_F*68];     // [K][68] transposed, padded
    __shared__ float s_sum[64], s_sq[64];
    float* __restrict__ Z = target ? g_he : g_hn;

    int tid = threadIdx.x;
    if (tid < 64){ s_sum[tid]=0.f; s_sq[tid]=0.f; }
    for (int i=tid; i<K*64; i+=256) Ws[i] = W[i];
    int r0 = blockIdx.x*64;
    for (int i=tid; i<64*K; i+=256){
        int r = i / K, k = i - r*K;
        int rr = r0 + r;
        Xs[k*68+r] = (rr < rows) ? X[(size_t)rr*K + k] : 0.f;
    }
    __syncthreads();

    int tx = tid & 15, ty = tid >> 4;
    u64 acc[4][2];
#pragma unroll
    for (int i=0;i<4;i++){ acc[i][0]=0ull; acc[i][1]=0ull; }

    for (int k=0;k<K;k++){
        float4 av = *(const float4*)(Xs + k*68 + 4*ty);
        u64x2 bv = *(const u64x2*)(Ws + k*64 + 4*tx);
        u64 a2[4] = { dup_f32x2(av.x), dup_f32x2(av.y),
                      dup_f32x2(av.z), dup_f32x2(av.w) };
#pragma unroll
        for (int i=0;i<4;i++){
            acc[i][0] = fma_f32x2(a2[i], bv.x, acc[i][0]);
            acc[i][1] = fma_f32x2(a2[i], bv.y, acc[i][1]);
        }
    }

    float4 bb = *(const float4*)(bias + 4*tx);
    float b4[4]={bb.x,bb.y,bb.z,bb.w};
    float lsum[4]={0,0,0,0}, lsq[4]={0,0,0,0};
#pragma unroll
    for (int i=0;i<4;i++){
        int rr = r0 + 4*ty + i;
        if (rr < rows){
            float z[4];
            unpack_f32x2(acc[i][0], z[0], z[1]);
            unpack_f32x2(acc[i][1], z[2], z[3]);
#pragma unroll
            for (int j=0;j<4;j++) z[j] += b4[j];
            *(float4*)(Z + (size_t)rr*64 + 4*tx) = make_float4(z[0],z[1],z[2],z[3]);
#pragma unroll
            for (int j=0;j<4;j++){ lsum[j]+=z[j]; lsq[j]+=z[j]*z[j]; }
        }
    }
#pragma unroll
    for (int j=0;j<4;j++){
        atomicAdd(&s_sum[4*tx+j], lsum[j]);
        atomicAdd(&s_sq [4*tx+j], lsq[j]);
    }
    __syncthreads();
    if (tid < 64){
        atomicAdd(&g_stats[tid],     s_sum[tid]);
        atomicAdd(&g_stats[128+tid], s_sq[tid]);
    }
}

// ---------------- BN finalize: fold mean/var into scale/shift -------------
__global__ void k_finalize(const float* __restrict__ gamma,
                           const float* __restrict__ beta,
                           float cntInv, int off, int ncols)
{
    int c = threadIdx.x;
    if (c < ncols){
        float m = g_stats[off+c]*cntInv;
        float v = g_stats[128+off+c]*cntInv - m*m;
        float a = gamma[c]*rsqrtf(v + BN_EPS);
        g_scale[off+c] = a;
        g_shift[off+c] = beta[c] - m*a;
    }
}

// ---------------- embedding activation: h = silu(scale*z+shift) in place --
__global__ void k_embed_act(int target, int n)
{
    float* __restrict__ H = target ? g_he : g_hn;
    int i = blockIdx.x*256 + threadIdx.x;
    if (i < n){
        int c = i & 63;
        float y = g_scale[c]*H[i] + g_shift[c];
        H[i] = siluf_(y);
    }
}

// ---------------- conv GEMM: z[e][0:64]=h_cat@Wm+bm, z[e][64:128]=h_cat@Wg+bg
// persistent blocks, 64-edge x 128-col tiles, K-chunks of 32 (3 segs x 2)
// inner loop on packed fma.rn.f32x2 (FFMA2): halves FMA-pipe issue slots
__global__ __launch_bounds__(256,2) void k_conv_gemm(
    const int* __restrict__ src, const int* __restrict__ dst,
    const float* __restrict__ Wm, const float* __restrict__ Wg,
    const float* __restrict__ bm, const float* __restrict__ bg)
{
    __shared__ float Ws[32*128];   // [k][128]: cols 0:64 = Wm, 64:128 = Wg
    __shared__ float As[32*68];    // [k][68] transposed edges, padded
    __shared__ float s_sum[128], s_sq[128];

    int tid = threadIdx.x;
    int tx = tid & 15, ty = tid >> 4;
    float4 bmv = *(const float4*)(bm + 4*tx);
    float4 bgv = *(const float4*)(bg + 4*tx);
    float bmr[4]={bmv.x,bmv.y,bmv.z,bmv.w};
    float bgr[4]={bgv.x,bgv.y,bgv.z,bgv.w};
    float sS[8]={0,0,0,0,0,0,0,0}, sQ[8]={0,0,0,0,0,0,0,0};

    for (int tile = blockIdx.x; tile < NTILES; tile += gridDim.x){
        int e0 = tile*64;
        u64 accM[4][2], accG[4][2];
#pragma unroll
        for (int i=0;i<4;i++){
            accM[i][0]=0ull; accM[i][1]=0ull;
            accG[i][0]=0ull; accG[i][1]=0ull;
        }

        for (int seg=0; seg<3; seg++){
            for (int kc=0; kc<2; kc++){
                int kbase = seg*64 + kc*32;
                __syncthreads();
                // weights chunk: 32 x 128 floats = 1024 float4
                for (int i=tid; i<1024; i+=256){
                    int k = i >> 5, cg = i & 31;
                    const float* p = (cg < 16)
                        ? (Wm + (size_t)(kbase+k)*64 + cg*4)
                        : (Wg + (size_t)(kbase+k)*64 + (cg-16)*4);
                    ((float4*)Ws)[i] = *(const float4*)p;
                }
                // gathered A chunk: 64 edges x 32 k-values, transposed
                for (int i=tid; i<512; i+=256){
                    int e = i >> 3, q = i & 7;
                    int row;
                    const float* bp;
                    if (seg == 0){ row = src[e0+e]; bp = g_hn; }
                    else if (seg == 1){ row = dst[e0+e]; bp = g_hn; }
                    else { row = e0+e; bp = g_he; }
                    float4 v = *(const float4*)(bp + (size_t)row*64 + kc*32 + q*4);
                    int kl = q*4;
                    As[(kl+0)*68+e]=v.x; As[(kl+1)*68+e]=v.y;
                    As[(kl+2)*68+e]=v.z; As[(kl+3)*68+e]=v.w;
                }
                __syncthreads();
#pragma unroll 8
                for (int k=0;k<32;k++){
                    float4 av   = *(const float4*)(As + k*68 + 4*ty);
                    u64x2 bM = *(const u64x2*)(Ws + k*128 + 4*tx);
                    u64x2 bG = *(const u64x2*)(Ws + k*128 + 64 + 4*tx);
                    u64 a2[4] = { dup_f32x2(av.x), dup_f32x2(av.y),
                                  dup_f32x2(av.z), dup_f32x2(av.w) };
#pragma unroll
                    for (int i=0;i<4;i++){
                        accM[i][0] = fma_f32x2(a2[i], bM.x, accM[i][0]);
                        accM[i][1] = fma_f32x2(a2[i], bM.y, accM[i][1]);
                        accG[i][0] = fma_f32x2(a2[i], bG.x, accG[i][0]);
                        accG[i][1] = fma_f32x2(a2[i], bG.y, accG[i][1]);
                    }
                }
            }
        }
        // write z + accumulate stats
#pragma unroll
        for (int i=0;i<4;i++){
            size_t e = (size_t)e0 + 4*ty + i;
            float zm[4], zg[4];
            unpack_f32x2(accM[i][0], zm[0], zm[1]);
            unpack_f32x2(accM[i][1], zm[2], zm[3]);
            unpack_f32x2(accG[i][0], zg[0], zg[1]);
            unpack_f32x2(accG[i][1], zg[2], zg[3]);
#pragma unroll
            for (int j=0;j<4;j++){ zm[j]+=bmr[j]; zg[j]+=bgr[j]; }
            *(float4*)(g_z + e*128 + 4*tx)      = make_float4(zm[0],zm[1],zm[2],zm[3]);
            *(float4*)(g_z + e*128 + 64 + 4*tx) = make_float4(zg[0],zg[1],zg[2],zg[3]);
#pragma unroll
            for (int j=0;j<4;j++){
                sS[j]+=zm[j];   sQ[j]+=zm[j]*zm[j];
                sS[4+j]+=zg[j]; sQ[4+j]+=zg[j]*zg[j];
            }
        }
    }
    __syncthreads();
    if (tid < 128){ s_sum[tid]=0.f; s_sq[tid]=0.f; }
    __syncthreads();
#pragma unroll
    for (int j=0;j<4;j++){
        atomicAdd(&s_sum[4*tx+j],    sS[j]);   atomicAdd(&s_sq[4*tx+j],    sQ[j]);
        atomicAdd(&s_sum[64+4*tx+j], sS[4+j]); atomicAdd(&s_sq[64+4*tx+j], sQ[4+j]);
    }
    __syncthreads();
    if (tid < 128){
        atomicAdd(&g_stats[tid],     s_sum[tid]);
        atomicAdd(&g_stats[128+tid], s_sq[tid]);
    }
}

// ---------------- gated message + scatter-add onto dst -------------------
__global__ void k_scatter(const int* __restrict__ dst)
{
    int i = blockIdx.x*256 + threadIdx.x;
    if (i < N_EDGES*64){
        int e = i >> 6, c = i & 63;
        size_t zb = (size_t)e*128;
        float zm = g_z[zb + c];
        float zg = g_z[zb + 64 + c];
        float m = sigmoidf_ (g_scale[c]   *zm + g_shift[c]);
        float g = softplusf_(g_scale[64+c]*zg + g_shift[64+c]);
        atomicAdd(&g_agg[(size_t)dst[e]*64 + c], m*g);
    }
}

// ---------------- per-feature stats of agg over nodes --------------------
__global__ void k_node_stats()
{
    __shared__ float s_sum[64], s_sq[64];
    int tid = threadIdx.x;
    if (tid < 64){ s_sum[tid]=0.f; s_sq[tid]=0.f; }
    __syncthreads();
    float s=0.f, q=0.f;
    for (int i = blockIdx.x*256 + tid; i < N_NODES*64; i += gridDim.x*256){
        float v = g_agg[i]; s += v; q += v*v;
    }
    atomicAdd(&s_sum[tid & 63], s);
    atomicAdd(&s_sq [tid & 63], q);
    __syncthreads();
    if (tid < 64){
        atomicAdd(&g_stats[tid],     s_sum[tid]);
        atomicAdd(&g_stats[128+tid], s_sq[tid]);
    }
}

// ---------------- node update: h = sigmoid(bn(agg) + h) ------------------
__global__ void k_update()
{
    int i = blockIdx.x*256 + threadIdx.x;
    if (i < N_NODES*64){
        int c = i & 63;
        float x = g_scale[c]*g_agg[i] + g_shift[c] + g_hn[i];
        g_hn[i] = sigmoidf_(x);
    }
}

// ---------------- pooling ------------------------------------------------
__global__ void k_pool(const int* __restrict__ n2g)
{
    int i = blockIdx.x*256 + threadIdx.x;
    if (i < N_NODES*64){
        int n = i >> 6, c = i & 63;
        int g = n2g[n];
        atomicAdd(&g_pooled[g*64 + c], g_hn[i]);
        if (c == 0) atomicAdd(&g_cnt[g], 1.f);
    }
}

// ---------------- head: [128,64] -> bn+silu [128,10] -> [128,1] ----------
__global__ __launch_bounds__(128) void k_head(
    const float* __restrict__ Wfc, const float* __restrict__ bfc,
    const float* __restrict__ gfc, const float* __restrict__ befc,
    const float* __restrict__ Wout, const float* __restrict__ bout,
    float* __restrict__ out)
{
    __shared__ float sW[64*FCDIM];
    __shared__ float s_sum[FCDIM], s_sq[FCDIM];
    int tid = threadIdx.x;
    for (int i=tid; i<64*FCDIM; i+=128) sW[i] = Wfc[i];
    if (tid < FCDIM){ s_sum[tid]=0.f; s_sq[tid]=0.f; }
    __syncthreads();

    float inv = 1.f / fmaxf(g_cnt[tid], 1.f);
    float z[FCDIM];
#pragma unroll
    for (int j=0;j<FCDIM;j++) z[j] = bfc[j];
    for (int i=0;i<64;i++){
        float p = g_pooled[tid*64 + i] * inv;
#pragma unroll
        for (int j=0;j<FCDIM;j++) z[j] += p * sW[i*FCDIM + j];
    }
#pragma unroll
    for (int j=0;j<FCDIM;j++){
        atomicAdd(&s_sum[j], z[j]);
        atomicAdd(&s_sq[j],  z[j]*z[j]);
    }
    __syncthreads();

    float o = bout[0];
#pragma unroll
    for (int j=0;j<FCDIM;j++){
        float m = s_sum[j] * (1.f/NGRAPH);
        float v = s_sq[j]  * (1.f/NGRAPH) - m*m;
        float h = gfc[j]*(z[j]-m)*rsqrtf(v + BN_EPS) + befc[j];
        h = siluf_(h);
        o += h * Wout[j];
    }
    out[tid] = o;
}

// ---------------- launch -------------------------------------------------
extern "C" void kernel_launch(void* const* d_in, const int* in_sizes, int n_in,
                              void* d_out, int out_size)
{
    const float* node_feats = (const float*)d_in[0];
    const float* edge_feats = (const float*)d_in[1];
    const int*   src        = (const int*)d_in[2];
    const int*   dst        = (const int*)d_in[3];
    const int*   n2g        = (const int*)d_in[4];
    const float* W_ne=(const float*)d_in[5];  const float* b_ne=(const float*)d_in[6];
    const float* g_ne=(const float*)d_in[7];  const float* be_ne=(const float*)d_in[8];
    const float* W_ee=(const float*)d_in[9];  const float* b_ee=(const float*)d_in[10];
    const float* g_ee=(const float*)d_in[11]; const float* be_ee=(const float*)d_in[12];
    const float* Wm=(const float*)d_in[13];   const float* bm=(const float*)d_in[14];
    const float* gm=(const float*)d_in[15];   const float* bem=(const float*)d_in[16];
    const float* Wg=(const float*)d_in[17];   const float* bg=(const float*)d_in[18];
    const float* gg=(const float*)d_in[19];   const float* beg=(const float*)d_in[20];
    const float* gn=(const float*)d_in[21];   const float* ben=(const float*)d_in[22];
    const float* Wfc=(const float*)d_in[23];  const float* bfc=(const float*)d_in[24];
    const float* gfc=(const float*)d_in[25];  const float* befc=(const float*)d_in[26];
    const float* Wout=(const float*)d_in[27]; const float* bout=(const float*)d_in[28];
    float* out = (float*)d_out;
    (void)in_sizes; (void)n_in; (void)out_size;

    const int NE64 = N_NODES*64;            // 1,600,000
    const int EE64 = N_EDGES*64;            // 25,600,000

    // node embedding
    k_zero_stats<<<1,256>>>();
    k_embed_gemm<<<(N_NODES+63)/64,256>>>(node_feats, N_NODES, NODE_F, W_ne, b_ne, 0);
    k_finalize<<<1,128>>>(g_ne, be_ne, 1.f/N_NODES, 0, 64);
    k_embed_act<<<(NE64+255)/256,256>>>(0, NE64);

    // edge embedding
    k_zero_stats<<<1,256>>>();
    k_embed_gemm<<<N_EDGES/64,256>>>(edge_feats, N_EDGES, EDGE_F, W_ee, b_ee, 1);
    k_finalize<<<1,128>>>(g_ee, be_ee, 1.f/N_EDGES, 0, 64);
    k_embed_act<<<(EE64+255)/256,256>>>(1, EE64);

    // conv layers
    for (int l=0; l<3; l++){
        k_zero_stats<<<1,256>>>();
        k_conv_gemm<<<296,256>>>(src, dst,
                                 Wm + (size_t)l*KCAT*F, Wg + (size_t)l*KCAT*F,
                                 bm + l*F, bg + l*F);
        k_finalize<<<1,128>>>(gm + l*F, bem + l*F, 1.f/N_EDGES, 0, 64);
        k_finalize<<<1,128>>>(gg + l*F, beg + l*F, 1.f/N_EDGES, 64, 64);
        k_zero_agg<<<(NE64+255)/256,256>>>();
        k_scatter<<<EE64/256,256>>>(dst);
        k_zero_stats<<<1,256>>>();
        k_node_stats<<<592,256>>>();
        k_finalize<<<1,128>>>(gn + l*F, ben + l*F, 1.f/N_NODES, 0, 64);
        k_update<<<(NE64+255)/256,256>>>();
    }

    // pooling + head
    k_zero_pool<<<32,256>>>();
    k_pool<<<(NE64+255)/256,256>>>(n2g);
    k_head<<<1,128>>>(Wfc, bfc, gfc, befc, Wout, bout, out);
}

// round 9
// speedup vs baseline: 2.0190x; 2.0190x over previous
#include <cuda_runtime.h>
#include <cstdint>

#define N_NODES 25000
#define N_EDGES 400000
#define NGRAPH  128
#define F       64
#define KCAT    192
#define NODE_F  92
#define EDGE_F  41
#define FCDIM   10
#define BN_EPS  1e-5f
#define CTILES  (N_EDGES/128)   /* 3125 tiles of 128 edges */

// ---------------- scratch (device globals; no allocation allowed) ----------
__device__ __align__(128) float g_hn[N_NODES*F];               // 6.4 MB
__device__ __align__(128) float g_he[(size_t)N_EDGES*F];       // 102.4 MB
__device__ __align__(128) float g_z[(size_t)N_EDGES*128];      // 204.8 MB
__device__ __align__(128) float g_agg[N_NODES*F];              // 6.4 MB
__device__ __align__(128) float g_stats[256];                  // sum[128], sumsq[128]
__device__ __align__(128) float g_scale[128];
__device__ __align__(128) float g_shift[128];
__device__ __align__(128) float g_pooled[NGRAPH*F];
__device__ __align__(128) float g_cnt[NGRAPH];

// ---------------- math helpers ----------------
__device__ __forceinline__ float sigmoidf_(float x){ return 1.f/(1.f+expf(-x)); }
__device__ __forceinline__ float siluf_(float x){ return x/(1.f+expf(-x)); }
__device__ __forceinline__ float softplusf_(float x){
    return fmaxf(x,0.f) + log1pf(expf(-fabsf(x)));
}
__device__ __forceinline__ uint32_t tf32_rna(float x){
    uint32_t r; asm("cvt.rna.tf32.f32 %0, %1;" : "=r"(r) : "f"(x)); return r;
}

// packed fp32x2 (FFMA2 path) for the embedding GEMMs
typedef unsigned long long u64;
struct u64x2 { u64 x, y; };
__device__ __forceinline__ u64 dup_f32x2(float a){
    u64 r; asm("mov.b64 %0, {%1, %2};" : "=l"(r) : "f"(a), "f"(a)); return r;
}
__device__ __forceinline__ u64 fma_f32x2(u64 a, u64 b, u64 c){
    u64 d; asm("fma.rn.f32x2 %0, %1, %2, %3;" : "=l"(d) : "l"(a), "l"(b), "l"(c)); return d;
}
__device__ __forceinline__ void unpack_f32x2(u64 v, float& lo, float& hi){
    asm("mov.b64 {%0, %1}, %2;" : "=f"(lo), "=f"(hi) : "l"(v));
}

// mma.sync m16n8k8 tf32 (sm_80+ PTX; compiles for plain sm_103)
__device__ __forceinline__ void mma_tf32(float* d, const uint32_t* a, const uint32_t* b){
    asm volatile(
        "mma.sync.aligned.m16n8k8.row.col.f32.tf32.tf32.f32 "
        "{%0,%1,%2,%3}, {%4,%5,%6,%7}, {%8,%9}, {%0,%1,%2,%3};"
        : "+f"(d[0]), "+f"(d[1]), "+f"(d[2]), "+f"(d[3])
        : "r"(a[0]), "r"(a[1]), "r"(a[2]), "r"(a[3]), "r"(b[0]), "r"(b[1]));
}

// ---------------- zero kernels ----------------
__global__ void k_zero_stats(){ int i=threadIdx.x; if(i<256) g_stats[i]=0.f; }
__global__ void k_zero_agg(){ int i=blockIdx.x*256+threadIdx.x; if(i<N_NODES*F) g_agg[i]=0.f; }
__global__ void k_zero_pool(){ int i=blockIdx.x*256+threadIdx.x;
    if(i<NGRAPH*F) g_pooled[i]=0.f; if(i<NGRAPH) g_cnt[i]=0.f; }

// ---------------- embedding GEMM (FFMA2 scalar path, proven) --------------
__global__ __launch_bounds__(256) void k_embed_gemm(
    const float* __restrict__ X, int rows, int K,
    const float* __restrict__ W, const float* __restrict__ bias, int target)
{
    __shared__ float Ws[NODE_F*64];
    __shared__ float Xs[NODE_F*68];
    __shared__ float s_sum[64], s_sq[64];
    float* __restrict__ Z = target ? g_he : g_hn;

    int tid = threadIdx.x;
    if (tid < 64){ s_sum[tid]=0.f; s_sq[tid]=0.f; }
    for (int i=tid; i<K*64; i+=256) Ws[i] = W[i];
    int r0 = blockIdx.x*64;
    for (int i=tid; i<64*K; i+=256){
        int r = i / K, k = i - r*K;
        int rr = r0 + r;
        Xs[k*68+r] = (rr < rows) ? X[(size_t)rr*K + k] : 0.f;
    }
    __syncthreads();

    int tx = tid & 15, ty = tid >> 4;
    u64 acc[4][2];
#pragma unroll
    for (int i=0;i<4;i++){ acc[i][0]=0ull; acc[i][1]=0ull; }

    for (int k=0;k<K;k++){
        float4 av = *(const float4*)(Xs + k*68 + 4*ty);
        u64x2 bv = *(const u64x2*)(Ws + k*64 + 4*tx);
        u64 a2[4] = { dup_f32x2(av.x), dup_f32x2(av.y),
                      dup_f32x2(av.z), dup_f32x2(av.w) };
#pragma unroll
        for (int i=0;i<4;i++){
            acc[i][0] = fma_f32x2(a2[i], bv.x, acc[i][0]);
            acc[i][1] = fma_f32x2(a2[i], bv.y, acc[i][1]);
        }
    }

    float4 bb = *(const float4*)(bias + 4*tx);
    float b4[4]={bb.x,bb.y,bb.z,bb.w};
    float lsum[4]={0,0,0,0}, lsq[4]={0,0,0,0};
#pragma unroll
    for (int i=0;i<4;i++){
        int rr = r0 + 4*ty + i;
        if (rr < rows){
            float z[4];
            unpack_f32x2(acc[i][0], z[0], z[1]);
            unpack_f32x2(acc[i][1], z[2], z[3]);
#pragma unroll
            for (int j=0;j<4;j++) z[j] += b4[j];
            *(float4*)(Z + (size_t)rr*64 + 4*tx) = make_float4(z[0],z[1],z[2],z[3]);
#pragma unroll
            for (int j=0;j<4;j++){ lsum[j]+=z[j]; lsq[j]+=z[j]*z[j]; }
        }
    }
#pragma unroll
    for (int j=0;j<4;j++){
        atomicAdd(&s_sum[4*tx+j], lsum[j]);
        atomicAdd(&s_sq [4*tx+j], lsq[j]);
    }
    __syncthreads();
    if (tid < 64){
        atomicAdd(&g_stats[tid],     s_sum[tid]);
        atomicAdd(&g_stats[128+tid], s_sq[tid]);
    }
}

// ---------------- BN finalize: fold stats into scale/shift, zero after ----
__global__ void k_finalize(const float* __restrict__ gamma,
                           const float* __restrict__ beta,
                           float cntInv, int off, int ncols)
{
    int c = threadIdx.x;
    if (c < ncols){
        float m = g_stats[off+c]*cntInv;
        float v = g_stats[128+off+c]*cntInv - m*m;
        float a = gamma[c]*rsqrtf(v + BN_EPS);
        g_scale[off+c] = a;
        g_shift[off+c] = beta[c] - m*a;
        g_stats[off+c] = 0.f;
        g_stats[128+off+c] = 0.f;
    }
}

// ---------------- embedding activation ----------------
__global__ void k_embed_act(int target, int n)
{
    float* __restrict__ H = target ? g_he : g_hn;
    int i = blockIdx.x*256 + threadIdx.x;
    if (i < n){
        int c = i & 63;
        float y = g_scale[c]*H[i] + g_shift[c];
        H[i] = siluf_(y);
    }
}

// =================== mma.sync tf32 conv GEMM ===============================
// tile: 128 edges(M) x 128 outputs(N: 0:64=Wm branch, 64:128=Wg), K=192.
// 8 warps as 2(M)x4(N), warp tile 64x32, mma m16n8k8.
// B resident in smem ([k][n], stride 136, tf32). A gathered per 32-K chunk
// with register-staged double buffering. BN bias cancels -> raw acc to g_z.
// Per-column stats accumulated in epilogue registers across all tiles.

#define BSTRIDE 136
#define ASTRIDE 36
#define SMB_OFF 0                                /* 192*136*4 = 104448 B */
#define SMA0_OFF 104448                          /* 128*36*4  = 18432 B  */
#define SMA1_OFF (SMA0_OFF + 18432)              /* 122880 */
#define SMST_OFF (SMA1_OFF + 18432)              /* 141312: s_sum128+s_sq128 */
#define CONV_SMEM_BYTES (SMST_OFF + 1024)        /* 142336 */

__device__ __forceinline__ void conv_gather_regs(
    float4* stv, int c, size_t e0,
    const int* __restrict__ src, const int* __restrict__ dst, int tid)
{
    int seg = c >> 1, kc = (c & 1) * 32;
#pragma unroll
    for (int it = 0; it < 4; it++){
        int i = tid + it*256;              // 0..1023
        int e = i >> 3, q = i & 7;
        size_t row; const float* bp;
        if (seg == 0){ row = (size_t)src[e0+e]; bp = g_hn; }
        else if (seg == 1){ row = (size_t)dst[e0+e]; bp = g_hn; }
        else { row = e0 + e; bp = g_he; }
        stv[it] = *(const float4*)(bp + row*64 + kc + q*4);
    }
}

__device__ __forceinline__ void conv_store_regs(float* abuf, const float4* stv, int tid)
{
#pragma unroll
    for (int it = 0; it < 4; it++){
        int i = tid + it*256;
        int e = i >> 3, q = i & 7;
        uint4 t;
        t.x = tf32_rna(stv[it].x); t.y = tf32_rna(stv[it].y);
        t.z = tf32_rna(stv[it].z); t.w = tf32_rna(stv[it].w);
        *(uint4*)(abuf + e*ASTRIDE + q*4) = t;
    }
}

__global__ void __launch_bounds__(256,1) k_conv_mma(
    const int* __restrict__ src, const int* __restrict__ dst,
    const float* __restrict__ Wm, const float* __restrict__ Wg)
{
    extern __shared__ char smem[];
    float* Bs = (float*)(smem + SMB_OFF);
    float* A0 = (float*)(smem + SMA0_OFF);
    float* A1 = (float*)(smem + SMA1_OFF);
    float* s_sum = (float*)(smem + SMST_OFF);
    float* s_sq  = s_sum + 128;

    int tid = threadIdx.x, wid = tid >> 5, lane = tid & 31;
    int wm = wid & 1, wn = wid >> 1;            // warp grid 2(M) x 4(N)
    int m0 = wm * 64, n0 = wn * 32;
    int lr = lane >> 2, lc = lane & 3;

    // fill B resident: Bs[k][n] = tf32(n<64 ? Wm[k][n] : Wg[k][n-64])
    for (int i = tid; i < 6144; i += 256){
        int k = i >> 5, q = i & 31;
        const float* p = (q < 16) ? (Wm + (size_t)k*64 + q*4)
                                  : (Wg + (size_t)k*64 + (q-16)*4);
        float4 v = *(const float4*)p;
        int n = (q < 16) ? q*4 : 64 + (q-16)*4;
        uint4 t;
        t.x = tf32_rna(v.x); t.y = tf32_rna(v.y);
        t.z = tf32_rna(v.z); t.w = tf32_rna(v.w);
        *(uint4*)(Bs + k*BSTRIDE + n) = t;
    }
    __syncthreads();

    float sS[8] = {0,0,0,0,0,0,0,0}, sQ[8] = {0,0,0,0,0,0,0,0};

    for (int tile = blockIdx.x; tile < CTILES; tile += gridDim.x){
        size_t e0 = (size_t)tile * 128;
        float acc[4][4][4];
#pragma unroll
        for (int mi=0;mi<4;mi++)
#pragma unroll
            for (int ni=0;ni<4;ni++)
#pragma unroll
                for (int r=0;r<4;r++) acc[mi][ni][r] = 0.f;

        float4 stv[4];
        conv_gather_regs(stv, 0, e0, src, dst, tid);
        conv_store_regs(A0, stv, tid);
        __syncthreads();

        for (int c = 0; c < 6; c++){
            if (c < 5) conv_gather_regs(stv, c+1, e0, src, dst, tid);
            const float* As = (c & 1) ? A1 : A0;
#pragma unroll
            for (int k8 = 0; k8 < 4; k8++){
                int kg = c*32 + k8*8 + lc;
                uint32_t bf[4][2];
#pragma unroll
                for (int ni=0;ni<4;ni++){
                    int n = n0 + ni*8 + lr;
                    bf[ni][0] = __float_as_uint(Bs[kg*BSTRIDE + n]);
                    bf[ni][1] = __float_as_uint(Bs[(kg+4)*BSTRIDE + n]);
                }
                uint32_t af[4][4];
                int kl = k8*8 + lc;
#pragma unroll
                for (int mi=0;mi<4;mi++){
                    int row = m0 + mi*16 + lr;
                    af[mi][0] = __float_as_uint(As[row*ASTRIDE + kl]);
                    af[mi][1] = __float_as_uint(As[(row+8)*ASTRIDE + kl]);
                    af[mi][2] = __float_as_uint(As[row*ASTRIDE + kl + 4]);
                    af[mi][3] = __float_as_uint(As[(row+8)*ASTRIDE + kl + 4]);
                }
#pragma unroll
                for (int mi=0;mi<4;mi++)
#pragma unroll
                    for (int ni=0;ni<4;ni++)
                        mma_tf32(acc[mi][ni], af[mi], bf[ni]);
            }
            if (c < 5){
                __syncthreads();
                conv_store_regs((c & 1) ? A0 : A1, stv, tid);
                __syncthreads();
            }
        }

        // epilogue: write z + accumulate column stats in regs
#pragma unroll
        for (int mi=0;mi<4;mi++){
            int row = m0 + mi*16 + lr;
#pragma unroll
            for (int ni=0;ni<4;ni++){
                int col = n0 + ni*8 + 2*lc;
                float d0=acc[mi][ni][0], d1=acc[mi][ni][1];
                float d2=acc[mi][ni][2], d3=acc[mi][ni][3];
                *(float2*)(g_z + (e0+row)*128 + col)   = make_float2(d0,d1);
                *(float2*)(g_z + (e0+row+8)*128 + col) = make_float2(d2,d3);
                sS[ni*2+0] += d0 + d2;  sQ[ni*2+0] += d0*d0 + d2*d2;
                sS[ni*2+1] += d1 + d3;  sQ[ni*2+1] += d1*d1 + d3*d3;
            }
        }
        __syncthreads();
    }

    // block-level stat reduction -> global
    if (tid < 128){ s_sum[tid]=0.f; s_sq[tid]=0.f; }
    __syncthreads();
#pragma unroll
    for (int ni=0;ni<4;ni++){
        int col = n0 + ni*8 + 2*lc;
        atomicAdd(&s_sum[col],   sS[ni*2+0]); atomicAdd(&s_sq[col],   sQ[ni*2+0]);
        atomicAdd(&s_sum[col+1], sS[ni*2+1]); atomicAdd(&s_sq[col+1], sQ[ni*2+1]);
    }
    __syncthreads();
    if (tid < 128){
        atomicAdd(&g_stats[tid],     s_sum[tid]);
        atomicAdd(&g_stats[128+tid], s_sq[tid]);
    }
}

// ---------------- gated message + vectorized scatter-add ------------------
__global__ void k_scatter(const int* __restrict__ dst)
{
    size_t i = (size_t)blockIdx.x*256 + threadIdx.x;
    if (i < (size_t)N_EDGES*16){
        int e = (int)(i >> 4), cg = (int)(i & 15);
        int c = cg * 4;
        float4 zm = *(const float4*)(g_z + (size_t)e*128 + c);
        float4 zg = *(const float4*)(g_z + (size_t)e*128 + 64 + c);
        float r0 = sigmoidf_(g_scale[c+0]*zm.x + g_shift[c+0]) *
                   softplusf_(g_scale[64+c+0]*zg.x + g_shift[64+c+0]);
        float r1 = sigmoidf_(g_scale[c+1]*zm.y + g_shift[c+1]) *
                   softplusf_(g_scale[64+c+1]*zg.y + g_shift[64+c+1]);
        float r2 = sigmoidf_(g_scale[c+2]*zm.z + g_shift[c+2]) *
                   softplusf_(g_scale[64+c+2]*zg.z + g_shift[64+c+2]);
        float r3 = sigmoidf_(g_scale[c+3]*zm.w + g_shift[c+3]) *
                   softplusf_(g_scale[64+c+3]*zg.w + g_shift[64+c+3]);
        float* p = g_agg + (size_t)dst[e]*64 + c;
        asm volatile("red.global.add.v4.f32 [%0], {%1, %2, %3, %4};"
                     :: "l"(p), "f"(r0), "f"(r1), "f"(r2), "f"(r3) : "memory");
    }
}

// ---------------- per-feature stats of agg over nodes ---------------------
__global__ void k_node_stats()
{
    __shared__ float s_sum[64], s_sq[64];
    int tid = threadIdx.x;
    if (tid < 64){ s_sum[tid]=0.f; s_sq[tid]=0.f; }
    __syncthreads();
    float s=0.f, q=0.f;
    for (int i = blockIdx.x*256 + tid; i < N_NODES*64; i += gridDim.x*256){
        float v = g_agg[i]; s += v; q += v*v;
    }
    atomicAdd(&s_sum[tid & 63], s);
    atomicAdd(&s_sq [tid & 63], q);
    __syncthreads();
    if (tid < 64){
        atomicAdd(&g_stats[tid],     s_sum[tid]);
        atomicAdd(&g_stats[128+tid], s_sq[tid]);
    }
}

// ---------------- node update: h = sigmoid(bn(agg) + h) -------------------
__global__ void k_update()
{
    int i = blockIdx.x*256 + threadIdx.x;
    if (i < N_NODES*64){
        int c = i & 63;
        float x = g_scale[c]*g_agg[i] + g_shift[c] + g_hn[i];
        g_hn[i] = sigmoidf_(x);
    }
}

// ---------------- pooling -------------------------------------------------
__global__ void k_pool(const int* __restrict__ n2g)
{
    int i = blockIdx.x*256 + threadIdx.x;
    if (i < N_NODES*64){
        int n = i >> 6, c = i & 63;
        int g = n2g[n];
        atomicAdd(&g_pooled[g*64 + c], g_hn[i]);
        if (c == 0) atomicAdd(&g_cnt[g], 1.f);
    }
}

// ---------------- head ----------------------------------------------------
__global__ __launch_bounds__(128) void k_head(
    const float* __restrict__ Wfc, const float* __restrict__ bfc,
    const float* __restrict__ gfc, const float* __restrict__ befc,
    const float* __restrict__ Wout, const float* __restrict__ bout,
    float* __restrict__ out)
{
    __shared__ float sW[64*FCDIM];
    __shared__ float s_sum[FCDIM], s_sq[FCDIM];
    int tid = threadIdx.x;
    for (int i=tid; i<64*FCDIM; i+=128) sW[i] = Wfc[i];
    if (tid < FCDIM){ s_sum[tid]=0.f; s_sq[tid]=0.f; }
    __syncthreads();

    float inv = 1.f / fmaxf(g_cnt[tid], 1.f);
    float z[FCDIM];
#pragma unroll
    for (int j=0;j<FCDIM;j++) z[j] = bfc[j];
    for (int i=0;i<64;i++){
        float p = g_pooled[tid*64 + i] * inv;
#pragma unroll
        for (int j=0;j<FCDIM;j++) z[j] += p * sW[i*FCDIM + j];
    }
#pragma unroll
    for (int j=0;j<FCDIM;j++){
        atomicAdd(&s_sum[j], z[j]);
        atomicAdd(&s_sq[j],  z[j]*z[j]);
    }
    __syncthreads();

    float o = bout[0];
#pragma unroll
    for (int j=0;j<FCDIM;j++){
        float m = s_sum[j] * (1.f/NGRAPH);
        float v = s_sq[j]  * (1.f/NGRAPH) - m*m;
        float h = gfc[j]*(z[j]-m)*rsqrtf(v + BN_EPS) + befc[j];
        h = siluf_(h);
        o += h * Wout[j];
    }
    out[tid] = o;
}

// ---------------- launch --------------------------------------------------
extern "C" void kernel_launch(void* const* d_in, const int* in_sizes, int n_in,
                              void* d_out, int out_size)
{
    const float* node_feats = (const float*)d_in[0];
    const float* edge_feats = (const float*)d_in[1];
    const int*   src        = (const int*)d_in[2];
    const int*   dst        = (const int*)d_in[3];
    const int*   n2g        = (const int*)d_in[4];
    const float* W_ne=(const float*)d_in[5];  const float* b_ne=(const float*)d_in[6];
    const float* g_ne=(const float*)d_in[7];  const float* be_ne=(const float*)d_in[8];
    const float* W_ee=(const float*)d_in[9];  const float* b_ee=(const float*)d_in[10];
    const float* g_ee=(const float*)d_in[11]; const float* be_ee=(const float*)d_in[12];
    const float* Wm=(const float*)d_in[13];
    const float* gm=(const float*)d_in[15];   const float* bem=(const float*)d_in[16];
    const float* Wg=(const float*)d_in[17];
    const float* gg=(const float*)d_in[19];   const float* beg=(const float*)d_in[20];
    const float* gn=(const float*)d_in[21];   const float* ben=(const float*)d_in[22];
    const float* Wfc=(const float*)d_in[23];  const float* bfc=(const float*)d_in[24];
    const float* gfc=(const float*)d_in[25];  const float* befc=(const float*)d_in[26];
    const float* Wout=(const float*)d_in[27]; const float* bout=(const float*)d_in[28];
    float* out = (float*)d_out;
    (void)in_sizes; (void)n_in; (void)out_size;

    cudaFuncSetAttribute(k_conv_mma, cudaFuncAttributeMaxDynamicSharedMemorySize,
                         CONV_SMEM_BYTES);

    const int NE64 = N_NODES*64;            // 1,600,000
    const int EE64 = N_EDGES*64;            // 25,600,000

    k_zero_stats<<<1,256>>>();

    // node embedding
    k_embed_gemm<<<(N_NODES+63)/64,256>>>(node_feats, N_NODES, NODE_F, W_ne, b_ne, 0);
    k_finalize<<<1,128>>>(g_ne, be_ne, 1.f/N_NODES, 0, 64);
    k_embed_act<<<(NE64+255)/256,256>>>(0, NE64);

    // edge embedding
    k_embed_gemm<<<N_EDGES/64,256>>>(edge_feats, N_EDGES, EDGE_F, W_ee, b_ee, 1);
    k_finalize<<<1,128>>>(g_ee, be_ee, 1.f/N_EDGES, 0, 64);
    k_embed_act<<<(EE64+255)/256,256>>>(1, EE64);

    // conv layers
    for (int l=0; l<3; l++){
        k_conv_mma<<<148,256,CONV_SMEM_BYTES>>>(src, dst,
                                 Wm + (size_t)l*KCAT*F, Wg + (size_t)l*KCAT*F);
        k_finalize<<<1,128>>>(gm + l*F, bem + l*F, 1.f/N_EDGES, 0, 64);
        k_finalize<<<1,128>>>(gg + l*F, beg + l*F, 1.f/N_EDGES, 64, 64);
        k_zero_agg<<<(NE64+255)/256,256>>>();
        k_scatter<<<(N_EDGES*16)/256,256>>>(dst);
        k_node_stats<<<592,256>>>();
        k_finalize<<<1,128>>>(gn + l*F, ben + l*F, 1.f/N_NODES, 0, 64);
        k_update<<<(NE64+255)/256,256>>>();
    }

    // pooling + head
    k_zero_pool<<<32,256>>>();
    k_pool<<<(NE64+255)/256,256>>>(n2g);
    k_head<<<1,128>>>(Wfc, bfc, gfc, befc, Wout, bout, out);
}